// round 1
// baseline (speedup 1.0000x reference)
#include <cuda_runtime.h>
#include <cstdint>

// Problem constants (fixed shapes per reference setup_inputs)
#define NCLASS 19
#define HW (512 * 1024)        // 524288
#define NBATCH 8
#define NPIX (NBATCH * HW)     // 4194304 pixels
#define NVEC (NPIX / 4)        // float4 groups

// Scratch counters in device globals (no allocation allowed)
__device__ unsigned int g_pred_cnt[NCLASS];
__device__ unsigned int g_true_cnt[NCLASS];
__device__ unsigned int g_inter_cnt[NCLASS];

__global__ void iou_zero_kernel() {
    int t = threadIdx.x;
    if (t < NCLASS) {
        g_pred_cnt[t] = 0u;
        g_true_cnt[t] = 0u;
        g_inter_cnt[t] = 0u;
    }
}

// Each thread handles 4 consecutive pixels (float4 per channel).
// preds layout: [B, C, H, W] -> elem offset = b*C*HW + c*HW + s, s = spatial idx.
// For linear pixel i = b*HW + s: offset = i + b*(C-1)*HW + c*HW.
__global__ __launch_bounds__(256)
void iou_accum_kernel(const float* __restrict__ preds,
                      const int*   __restrict__ targets) {
    __shared__ unsigned int s_pred[NCLASS];
    __shared__ unsigned int s_true[NCLASS];
    __shared__ unsigned int s_inter[NCLASS];

    int t = threadIdx.x;
    if (t < NCLASS) {
        s_pred[t]  = 0u;
        s_true[t]  = 0u;
        s_inter[t] = 0u;
    }
    __syncthreads();

    unsigned int vidx = blockIdx.x * blockDim.x + threadIdx.x;  // float4 index
    if (vidx < NVEC) {
        unsigned int i = vidx * 4;                  // pixel index
        unsigned int b = i / HW;                    // batch
        size_t base = (size_t)i + (size_t)b * (size_t)(NCLASS - 1) * HW;
        const float4* p4 = reinterpret_cast<const float4*>(preds + base);
        const size_t ch_stride4 = HW / 4;           // float4 stride per channel

        // Argmax over channels for 4 pixels; strict > keeps first max (JAX semantics)
        float4 best = p4[0];
        int bx = 0, by = 0, bz = 0, bw = 0;
#pragma unroll
        for (int c = 1; c < NCLASS; ++c) {
            float4 v = p4[(size_t)c * ch_stride4];
            if (v.x > best.x) { best.x = v.x; bx = c; }
            if (v.y > best.y) { best.y = v.y; by = c; }
            if (v.z > best.z) { best.z = v.z; bz = c; }
            if (v.w > best.w) { best.w = v.w; bw = c; }
        }

        int4 tg = reinterpret_cast<const int4*>(targets)[vidx];

        atomicAdd(&s_pred[bx], 1u);
        atomicAdd(&s_pred[by], 1u);
        atomicAdd(&s_pred[bz], 1u);
        atomicAdd(&s_pred[bw], 1u);

        atomicAdd(&s_true[tg.x], 1u);
        atomicAdd(&s_true[tg.y], 1u);
        atomicAdd(&s_true[tg.z], 1u);
        atomicAdd(&s_true[tg.w], 1u);

        if (bx == tg.x) atomicAdd(&s_inter[bx], 1u);
        if (by == tg.y) atomicAdd(&s_inter[by], 1u);
        if (bz == tg.z) atomicAdd(&s_inter[bz], 1u);
        if (bw == tg.w) atomicAdd(&s_inter[bw], 1u);
    }

    __syncthreads();
    if (t < NCLASS) {
        if (s_pred[t])  atomicAdd(&g_pred_cnt[t],  s_pred[t]);
        if (s_true[t])  atomicAdd(&g_true_cnt[t],  s_true[t]);
        if (s_inter[t]) atomicAdd(&g_inter_cnt[t], s_inter[t]);
    }
}

// Output layout: out[0..17] = iou for classes 1..18, out[18] = mean_iou
__global__ void iou_finalize_kernel(float* __restrict__ out) {
    __shared__ float iou[NCLASS];
    int t = threadIdx.x;
    if (t < NCLASS) {
        unsigned int inter = g_inter_cnt[t];
        unsigned int pc = g_pred_cnt[t];
        unsigned int tc = g_true_cnt[t];
        unsigned int uni = pc + tc - inter;
        float v = (tc > 0u) ? ((float)inter / (float)max(uni, 1u)) : 0.0f;
        iou[t] = v;
        if (t >= 1) out[t - 1] = v;
    }
    __syncthreads();
    if (t == 0) {
        float s = 0.0f;
        for (int c = 1; c < NCLASS; ++c) s += iou[c];
        out[NCLASS - 1] = s / (float)(NCLASS - 1);
    }
}

extern "C" void kernel_launch(void* const* d_in, const int* in_sizes, int n_in,
                              void* d_out, int out_size) {
    const float* preds   = (const float*)d_in[0];
    const int*   targets = (const int*)d_in[1];
    float*       out     = (float*)d_out;

    iou_zero_kernel<<<1, 32>>>();

    const int threads = 256;
    const int blocks = (NVEC + threads - 1) / threads;  // 4096
    iou_accum_kernel<<<blocks, threads>>>(preds, targets);

    iou_finalize_kernel<<<1, 32>>>(out);
}

// round 3
// speedup vs baseline: 1.0611x; 1.0611x over previous
#include <cuda_runtime.h>
#include <cstdint>

// Problem constants (fixed shapes per reference setup_inputs)
#define NCLASS 19
#define HW (512 * 1024)        // 524288
#define NBATCH 8
#define NPIX (NBATCH * HW)     // 4194304 pixels
#define NVEC (NPIX / 4)        // 1048576 float4 groups
#define THREADS 256
#define NBLOCKS (NVEC / THREADS)  // 4096, exact

// Scratch counters in device globals (no allocation allowed).
// Zero-initialized at module load; the finalizing block resets them to zero
// after each run, so every graph replay starts from a clean state.
__device__ unsigned int g_pred_cnt[NCLASS];
__device__ unsigned int g_true_cnt[NCLASS];
__device__ unsigned int g_inter_cnt[NCLASS];
__device__ unsigned int g_ticket;

// Single fused kernel:
//  1) per-block shared-memory histograms (argmax over 19 channels, 4 px/thread)
//  2) global REDG accumulate
//  3) last block (threadfence-reduction ticket) computes IoU, writes out,
//     and resets all global scratch to zero.
__global__ __launch_bounds__(THREADS)
void iou_fused_kernel(const float* __restrict__ preds,
                      const int*   __restrict__ targets,
                      float*       __restrict__ out) {
    __shared__ unsigned int s_pred[NCLASS];
    __shared__ unsigned int s_true[NCLASS];
    __shared__ unsigned int s_inter[NCLASS];
    __shared__ bool s_is_last;

    const int t = threadIdx.x;
    if (t < NCLASS) {
        s_pred[t]  = 0u;
        s_true[t]  = 0u;
        s_inter[t] = 0u;
    }
    __syncthreads();

    // ---- accumulate phase ----
    const unsigned int vidx = blockIdx.x * THREADS + t;   // float4 index
    {
        const unsigned int i = vidx * 4;                  // pixel index
        const unsigned int b = i / HW;                    // batch
        // preds elem offset for (b, c, s): b*C*HW + c*HW + s = i + b*(C-1)*HW + c*HW
        const size_t base = (size_t)i + (size_t)b * (size_t)(NCLASS - 1) * HW;
        const float4* p4 = reinterpret_cast<const float4*>(preds + base);
        const size_t ch_stride4 = HW / 4;

        // Argmax over channels; strict > keeps the first max (JAX argmax semantics)
        float4 best = p4[0];
        int bx = 0, by = 0, bz = 0, bw = 0;
#pragma unroll
        for (int c = 1; c < NCLASS; ++c) {
            float4 v = p4[(size_t)c * ch_stride4];
            if (v.x > best.x) { best.x = v.x; bx = c; }
            if (v.y > best.y) { best.y = v.y; by = c; }
            if (v.z > best.z) { best.z = v.z; bz = c; }
            if (v.w > best.w) { best.w = v.w; bw = c; }
        }

        const int4 tg = reinterpret_cast<const int4*>(targets)[vidx];

        atomicAdd(&s_pred[bx], 1u);
        atomicAdd(&s_pred[by], 1u);
        atomicAdd(&s_pred[bz], 1u);
        atomicAdd(&s_pred[bw], 1u);

        atomicAdd(&s_true[tg.x], 1u);
        atomicAdd(&s_true[tg.y], 1u);
        atomicAdd(&s_true[tg.z], 1u);
        atomicAdd(&s_true[tg.w], 1u);

        if (bx == tg.x) atomicAdd(&s_inter[bx], 1u);
        if (by == tg.y) atomicAdd(&s_inter[by], 1u);
        if (bz == tg.z) atomicAdd(&s_inter[bz], 1u);
        if (bw == tg.w) atomicAdd(&s_inter[bw], 1u);
    }

    __syncthreads();

    // ---- global accumulate + fence (per writing thread) ----
    if (t < NCLASS) {
        if (s_pred[t])  atomicAdd(&g_pred_cnt[t],  s_pred[t]);
        if (s_true[t])  atomicAdd(&g_true_cnt[t],  s_true[t]);
        if (s_inter[t]) atomicAdd(&g_inter_cnt[t], s_inter[t]);
        __threadfence();   // make this thread's global atomics visible device-wide
    }
    __syncthreads();

    // ---- ticket: last block to finish finalizes ----
    if (t == 0) {
        unsigned int old = atomicAdd(&g_ticket, 1u);
        s_is_last = (old == (unsigned int)(gridDim.x - 1));
    }
    __syncthreads();

    if (s_is_last) {
        __shared__ float iou[NCLASS];
        if (t < NCLASS) {
            // volatile reads: bypass L1, see the L2-resident atomic results
            unsigned int inter = *(volatile unsigned int*)&g_inter_cnt[t];
            unsigned int pc    = *(volatile unsigned int*)&g_pred_cnt[t];
            unsigned int tc    = *(volatile unsigned int*)&g_true_cnt[t];
            unsigned int uni = pc + tc - inter;
            float v = (tc > 0u) ? ((float)inter / (float)max(uni, 1u)) : 0.0f;
            iou[t] = v;
            if (t >= 1) out[t - 1] = v;
            // reset scratch for next graph replay
            g_pred_cnt[t]  = 0u;
            g_true_cnt[t]  = 0u;
            g_inter_cnt[t] = 0u;
        }
        __syncthreads();
        if (t == 0) {
            float s = 0.0f;
#pragma unroll
            for (int c = 1; c < NCLASS; ++c) s += iou[c];
            out[NCLASS - 1] = s / (float)(NCLASS - 1);
            g_ticket = 0u;
        }
    }
}

extern "C" void kernel_launch(void* const* d_in, const int* in_sizes, int n_in,
                              void* d_out, int out_size) {
    const float* preds   = (const float*)d_in[0];
    const int*   targets = (const int*)d_in[1];
    float*       out     = (float*)d_out;

    iou_fused_kernel<<<NBLOCKS, THREADS>>>(preds, targets, out);
}